// round 8
// baseline (speedup 1.0000x reference)
#include <cuda_runtime.h>

#ifndef PI_F
#define PI_F 3.14159265358979323846f
#endif

// ---------------- dims ----------------
// x: (8, 4096, 512)   rows = 32768
// u: rows x 1024, v: rows x 512
// DPB: 8192 circulant rows x 512
#define N_SEQ   4096
#define N_CIRC  8192
#define DMODEL  512
#define DEXP    1024
#define NROWS   32768

// ---------------- scratch (static device arrays; no allocations) ----------------
__device__ float  g_xn  [NROWS * DMODEL];
__device__ float  g_u   [NROWS * DEXP];
__device__ float  g_v   [NROWS * DMODEL];
__device__ float  g_ta  [N_CIRC * DMODEL];
__device__ float  g_tb  [N_CIRC * DMODEL];
__device__ float  g_At  [N_CIRC * DMODEL];     // time-domain kernel A (8192 x 512)
__device__ float2 g_Af  [DMODEL * N_CIRC];     // per-channel spectra (bitrev order, pre-scaled 1/8192)
__device__ float  g_conv[NROWS * DMODEL];
__device__ float  g_gate[NROWS * DEXP];

// ---------------- SimpleRMSNorm (+ optional ReLU), 512 cols ----------------
__global__ __launch_bounds__(128) void srms_kernel(const float* __restrict__ in,
                                                   float* __restrict__ out, int relu)
{
    long row = blockIdx.x;
    const float4* rp = reinterpret_cast<const float4*>(in + row * DMODEL);
    float4 v = rp[threadIdx.x];
    float s = v.x * v.x + v.y * v.y + v.z * v.z + v.w * v.w;
    #pragma unroll
    for (int o = 16; o > 0; o >>= 1) s += __shfl_xor_sync(0xffffffffu, s, o);
    __shared__ float ws[4];
    if ((threadIdx.x & 31) == 0) ws[threadIdx.x >> 5] = s;
    __syncthreads();
    float tot = ws[0] + ws[1] + ws[2] + ws[3];
    // x / (||x|| * 512^-0.5 + 1e-8)
    float scale = 1.0f / (sqrtf(tot) * 0.04419417382415922f + 1e-8f);
    float4 o4;
    o4.x = v.x * scale; o4.y = v.y * scale; o4.z = v.z * scale; o4.w = v.w * scale;
    if (relu) {
        o4.x = fmaxf(o4.x, 0.f); o4.y = fmaxf(o4.y, 0.f);
        o4.z = fmaxf(o4.z, 0.f); o4.w = fmaxf(o4.w, 0.f);
    }
    reinterpret_cast<float4*>(out + row * DMODEL)[threadIdx.x] = o4;
}

// ---------------- DPB layer-0: scalar pos -> 512, then srms+relu ----------------
__global__ __launch_bounds__(128) void dpb_in_kernel(const float* __restrict__ Wp,
                                                     const float* __restrict__ bp,
                                                     float* __restrict__ out)
{
    int m = blockIdx.x;
    float p;
    if (m == 0 || m == 4096) p = 0.f;
    else if (m < 4096)       p = (float)m;
    else                     p = (float)(m - 8192);
    float4 w = reinterpret_cast<const float4*>(Wp)[threadIdx.x];
    float4 b = reinterpret_cast<const float4*>(bp)[threadIdx.x];
    float4 v;
    v.x = fmaf(p, w.x, b.x); v.y = fmaf(p, w.y, b.y);
    v.z = fmaf(p, w.z, b.z); v.w = fmaf(p, w.w, b.w);
    float s = v.x * v.x + v.y * v.y + v.z * v.z + v.w * v.w;
    #pragma unroll
    for (int o = 16; o > 0; o >>= 1) s += __shfl_xor_sync(0xffffffffu, s, o);
    __shared__ float ws[4];
    if ((threadIdx.x & 31) == 0) ws[threadIdx.x >> 5] = s;
    __syncthreads();
    float tot = ws[0] + ws[1] + ws[2] + ws[3];
    float scale = 1.0f / (sqrtf(tot) * 0.04419417382415922f + 1e-8f);
    float4 o4;
    o4.x = fmaxf(v.x * scale, 0.f); o4.y = fmaxf(v.y * scale, 0.f);
    o4.z = fmaxf(v.z * scale, 0.f); o4.w = fmaxf(v.w * scale, 0.f);
    reinterpret_cast<float4*>(out + (long)m * DMODEL)[threadIdx.x] = o4;
}

// ---------------- SGEMM: C = epi(A@B + bias)  (128x128x8, 8x8 per thread) ----------------
template<bool SILU, bool GATE, bool RES>
__global__ __launch_bounds__(256) void sgemm_kernel(
    const float* __restrict__ A, const float* __restrict__ B,
    const float* __restrict__ bias, const float* __restrict__ mult,
    const float* __restrict__ res, float* __restrict__ C,
    int M, int N, int K)
{
    __shared__ float As[8][128];
    __shared__ float Bs[8][128];
    int tid = threadIdx.x;
    int aRow = tid >> 1;          // 0..127
    int aCol = (tid & 1) * 4;     // 0 or 4
    int bRow = tid >> 5;          // 0..7
    int bCol = (tid & 31) * 4;
    const float* Ag = A + ((long)blockIdx.y * 128 + aRow) * K + aCol;
    const float* Bg = B + (long)bRow * N + blockIdx.x * 128 + bCol;
    int ty = tid >> 4, tx = tid & 15;

    float acc[8][8];
    #pragma unroll
    for (int i = 0; i < 8; i++)
        #pragma unroll
        for (int j = 0; j < 8; j++) acc[i][j] = 0.f;

    for (int k0 = 0; k0 < K; k0 += 8) {
        float4 av = *reinterpret_cast<const float4*>(Ag + k0);
        As[aCol + 0][aRow] = av.x; As[aCol + 1][aRow] = av.y;
        As[aCol + 2][aRow] = av.z; As[aCol + 3][aRow] = av.w;
        *reinterpret_cast<float4*>(&Bs[bRow][bCol]) =
            *reinterpret_cast<const float4*>(Bg + (long)k0 * N);
        __syncthreads();
        #pragma unroll
        for (int k = 0; k < 8; k++) {
            float am[8], bn[8];
            *reinterpret_cast<float4*>(am)     = *reinterpret_cast<const float4*>(&As[k][ty * 8]);
            *reinterpret_cast<float4*>(am + 4) = *reinterpret_cast<const float4*>(&As[k][ty * 8 + 4]);
            *reinterpret_cast<float4*>(bn)     = *reinterpret_cast<const float4*>(&Bs[k][tx * 8]);
            *reinterpret_cast<float4*>(bn + 4) = *reinterpret_cast<const float4*>(&Bs[k][tx * 8 + 4]);
            #pragma unroll
            for (int i = 0; i < 8; i++)
                #pragma unroll
                for (int j = 0; j < 8; j++)
                    acc[i][j] = fmaf(am[i], bn[j], acc[i][j]);
        }
        __syncthreads();
    }

    #pragma unroll
    for (int i = 0; i < 8; i++) {
        long row = (long)blockIdx.y * 128 + ty * 8 + i;
        #pragma unroll
        for (int j = 0; j < 8; j++) {
            int col = blockIdx.x * 128 + tx * 8 + j;
            float vv = acc[i][j] + bias[col];
            if (SILU) vv = vv / (1.f + __expf(-vv));
            long idx = row * N + col;
            if (GATE) vv *= mult[idx];
            if (RES)  vv += res[idx];
            C[idx] = vv;
        }
    }
}

// ---------------- 8192-pt radix-2 FFT in shared memory ----------------
// Forward: Gentleman-Sande DIF, natural in -> bit-reversed out.
// Inverse: Cooley-Tukey DIT, bit-reversed in -> natural out (conjugate twiddles).
// Elementwise spectral multiply is done in bit-reversed order (consistent for both operands).
__device__ __forceinline__ void fft_fwd(float2* z, int tid)
{
    for (int s = 12; s >= 0; --s) {
        int len = 1 << s;
        for (int idx = tid; idx < 4096; idx += 512) {
            int j = idx & (len - 1);
            int i = ((idx >> s) << (s + 1)) + j;
            float2 u = z[i], w = z[i + len];
            z[i] = make_float2(u.x + w.x, u.y + w.y);
            float dx = u.x - w.x, dy = u.y - w.y;
            float ang = (-PI_F) * (float)j / (float)len;
            float sn, cs; __sincosf(ang, &sn, &cs);
            z[i + len] = make_float2(dx * cs - dy * sn, dx * sn + dy * cs);
        }
        __syncthreads();
    }
}

__device__ __forceinline__ void fft_inv(float2* z, int tid)
{
    for (int s = 0; s <= 12; ++s) {
        int len = 1 << s;
        for (int idx = tid; idx < 4096; idx += 512) {
            int j = idx & (len - 1);
            int i = ((idx >> s) << (s + 1)) + j;
            float ang = PI_F * (float)j / (float)len;
            float sn, cs; __sincosf(ang, &sn, &cs);
            float2 u = z[i], w = z[i + len];
            float txx = w.x * cs - w.y * sn;
            float tyy = w.x * sn + w.y * cs;
            z[i]       = make_float2(u.x + txx, u.y + tyy);
            z[i + len] = make_float2(u.x - txx, u.y - tyy);
        }
        __syncthreads();
    }
}

// Precompute per-channel kernel spectra (bitrev order, scaled by 1/8192)
__global__ __launch_bounds__(512) void af_kernel()
{
    extern __shared__ float2 z[];
    int c = blockIdx.x, tid = threadIdx.x;
    for (int m = tid; m < N_CIRC; m += 512)
        z[m] = make_float2(g_At[(long)m * DMODEL + c], 0.f);
    __syncthreads();
    fft_fwd(z, tid);
    const float inv = 1.0f / 8192.0f;
    for (int k = tid; k < N_CIRC; k += 512) {
        float2 v = z[k];
        g_Af[(long)c * N_CIRC + k] = make_float2(v.x * inv, v.y * inv);
    }
}

// Per-(batch, channel) circular convolution: out = irfft(fft(v_pad) * Af)[:4096]
__global__ __launch_bounds__(512) void conv_kernel()
{
    extern __shared__ float2 z[];
    int blk = blockIdx.x;
    int b = blk >> 9, c = blk & 511;
    int tid = threadIdx.x;
    const float* vp = g_v + ((long)b * N_SEQ) * DMODEL + c;
    for (int j = tid; j < N_SEQ; j += 512)
        z[j] = make_float2(vp[(long)j * DMODEL], 0.f);
    for (int j = N_SEQ + tid; j < N_CIRC; j += 512)
        z[j] = make_float2(0.f, 0.f);
    __syncthreads();
    fft_fwd(z, tid);
    const float2* af = g_Af + (long)c * N_CIRC;
    for (int k = tid; k < N_CIRC; k += 512) {
        float2 a = af[k], v = z[k];
        z[k] = make_float2(v.x * a.x - v.y * a.y, v.x * a.y + v.y * a.x);
    }
    __syncthreads();
    fft_inv(z, tid);
    float* op = g_conv + ((long)b * N_SEQ) * DMODEL + c;
    for (int i = tid; i < N_SEQ; i += 512)
        op[(long)i * DMODEL] = z[i].x;
}

// ---------------- host launch ----------------
static float* sym_f(const void* s) { void* p = nullptr; cudaGetSymbolAddress(&p, s); return (float*)p; }

extern "C" void kernel_launch(void* const* d_in, const int* in_sizes, int n_in,
                              void* d_out, int out_size)
{
    const float* x   = (const float*)d_in[0];
    const float* Wu  = (const float*)d_in[1];
    const float* bu  = (const float*)d_in[2];
    const float* Wv  = (const float*)d_in[3];
    const float* bv  = (const float*)d_in[4];
    const float* Wo1 = (const float*)d_in[5];
    const float* bo1 = (const float*)d_in[6];
    const float* Wo2 = (const float*)d_in[7];
    const float* bo2 = (const float*)d_in[8];
    const float* dWp = (const float*)d_in[9];
    const float* dbp = (const float*)d_in[10];
    const float* dW1 = (const float*)d_in[11];
    const float* db1 = (const float*)d_in[12];
    const float* dW2 = (const float*)d_in[13];
    const float* db2 = (const float*)d_in[14];
    const float* dW3 = (const float*)d_in[15];
    const float* db3 = (const float*)d_in[16];
    float* out = (float*)d_out;

    cudaFuncSetAttribute(af_kernel,   cudaFuncAttributeMaxDynamicSharedMemorySize, 65536);
    cudaFuncSetAttribute(conv_kernel, cudaFuncAttributeMaxDynamicSharedMemorySize, 65536);

    float* p_xn   = sym_f(g_xn);
    float* p_u    = sym_f(g_u);
    float* p_v    = sym_f(g_v);
    float* p_ta   = sym_f(g_ta);
    float* p_tb   = sym_f(g_tb);
    float* p_At   = sym_f(g_At);
    float* p_conv = sym_f(g_conv);
    float* p_gate = sym_f(g_gate);

    // 1) pre-norm
    srms_kernel<<<NROWS, 128>>>(x, p_xn, 0);
    // 2) u = silu(xn @ Wu + bu), v = silu(xn @ Wv + bv)
    sgemm_kernel<true,  false, false><<<dim3(8, 256), 256>>>(p_xn, Wu, bu, nullptr, nullptr, p_u, NROWS, DEXP,   DMODEL);
    sgemm_kernel<true,  false, false><<<dim3(4, 256), 256>>>(p_xn, Wv, bv, nullptr, nullptr, p_v, NROWS, DMODEL, DMODEL);
    // 3) DPB MLP over all 8192 circulant positions
    dpb_in_kernel<<<N_CIRC, 128>>>(dWp, dbp, p_ta);
    sgemm_kernel<false, false, false><<<dim3(4, 64), 256>>>(p_ta, dW1, db1, nullptr, nullptr, p_tb, N_CIRC, DMODEL, DMODEL);
    srms_kernel<<<N_CIRC, 128>>>(p_tb, p_ta, 1);
    sgemm_kernel<false, false, false><<<dim3(4, 64), 256>>>(p_ta, dW2, db2, nullptr, nullptr, p_tb, N_CIRC, DMODEL, DMODEL);
    srms_kernel<<<N_CIRC, 128>>>(p_tb, p_ta, 1);
    sgemm_kernel<false, false, false><<<dim3(4, 64), 256>>>(p_ta, dW3, db3, nullptr, nullptr, p_At, N_CIRC, DMODEL, DMODEL);
    // 4) kernel spectra + spectral convolution
    af_kernel<<<DMODEL, 512, 65536>>>();
    conv_kernel<<<NROWS / 8, 512, 65536>>>();   // 4096 blocks = batch(8) x channels(512)
    // 5) gate + output projection + residual
    sgemm_kernel<false, true,  false><<<dim3(8, 256), 256>>>(p_conv, Wo1, bo1, p_u, nullptr, p_gate, NROWS, DEXP,   DMODEL);
    sgemm_kernel<false, false, true ><<<dim3(4, 256), 256>>>(p_gate, Wo2, bo2, nullptr, x, out, NROWS, DMODEL, DEXP);
}

// round 13
// speedup vs baseline: 1.7693x; 1.7693x over previous
#include <cuda_runtime.h>
#include <cuda_bf16.h>
#include <cstdint>

#define PI_F 3.14159265358979323846f
#define N_SEQ   4096
#define N_CIRC  8192
#define DMODEL  512
#define NROWS   32768

// ---------------- scratch ----------------
__device__ float  g_u   [(size_t)NROWS * 1024];
__device__ float  g_v   [(size_t)NROWS * 512];
__device__ float  g_tb  [(size_t)N_CIRC * 512];
__device__ float  g_At  [(size_t)N_CIRC * 512];
__device__ float2 g_Af  [(size_t)512 * N_CIRC];
__device__ __nv_bfloat16 g_xn2  [(size_t)NROWS * 1024];
__device__ __nv_bfloat16 g_ta2  [(size_t)N_CIRC * 1024];
__device__ __nv_bfloat16 g_conv2[(size_t)NROWS * 1024];
__device__ __nv_bfloat16 g_gate2[(size_t)NROWS * 2048];
__device__ __nv_bfloat16 g_Wu3 [(size_t)1024 * 1536];
__device__ __nv_bfloat16 g_Wv3 [(size_t)512  * 1536];
__device__ __nv_bfloat16 g_Wo13[(size_t)1024 * 1536];
__device__ __nv_bfloat16 g_Wo23[(size_t)512  * 3072];
__device__ __nv_bfloat16 g_dW13[(size_t)512  * 1536];
__device__ __nv_bfloat16 g_dW23[(size_t)512  * 1536];
__device__ __nv_bfloat16 g_dW33[(size_t)512  * 1536];

// ---------------- helpers ----------------
__device__ __forceinline__ uint32_t s2u(const void* p){ return (uint32_t)__cvta_generic_to_shared(p); }
__device__ __forceinline__ uint32_t swz(uint32_t o){ return o ^ ((o >> 3) & 0x70); }
__device__ __forceinline__ void cp16(uint32_t d, const void* g){
    asm volatile("cp.async.cg.shared.global [%0], [%1], 16;" :: "r"(d), "l"(g));
}
__device__ __forceinline__ void hl_split(float x, __nv_bfloat16& h, __nv_bfloat16& l){
    h = __float2bfloat16(x);
    l = __float2bfloat16(x - __bfloat162float(h));
}
__device__ __forceinline__ void ldm4(uint32_t* r, uint32_t a){
    asm volatile("ldmatrix.sync.aligned.m8n8.x4.shared.b16 {%0,%1,%2,%3}, [%4];"
        : "=r"(r[0]),"=r"(r[1]),"=r"(r[2]),"=r"(r[3]) : "r"(a));
}
__device__ __forceinline__ void mmabf(float* d, const uint32_t* a, uint32_t b0, uint32_t b1){
    asm volatile("mma.sync.aligned.m16n8k16.row.col.f32.bf16.bf16.f32 "
        "{%0,%1,%2,%3}, {%4,%5,%6,%7}, {%8,%9}, {%0,%1,%2,%3};"
        : "+f"(d[0]),"+f"(d[1]),"+f"(d[2]),"+f"(d[3])
        : "r"(a[0]),"r"(a[1]),"r"(a[2]),"r"(a[3]), "r"(b0),"r"(b1));
}

// ---------------- SimpleRMSNorm(+ReLU) -> bf16 [hi|lo] ----------------
template<int RELU>
__global__ __launch_bounds__(128) void srms_hl_kernel(const float* __restrict__ in,
                                                      __nv_bfloat16* __restrict__ out)
{
    size_t row = blockIdx.x;
    float4 v = reinterpret_cast<const float4*>(in + row * DMODEL)[threadIdx.x];
    float s = v.x*v.x + v.y*v.y + v.z*v.z + v.w*v.w;
    #pragma unroll
    for (int o = 16; o > 0; o >>= 1) s += __shfl_xor_sync(0xffffffffu, s, o);
    __shared__ float ws[4];
    if ((threadIdx.x & 31) == 0) ws[threadIdx.x >> 5] = s;
    __syncthreads();
    float tot = ws[0] + ws[1] + ws[2] + ws[3];
    float scale = 1.0f / (sqrtf(tot) * 0.04419417382415922f + 1e-8f);
    float a[4] = { v.x*scale, v.y*scale, v.z*scale, v.w*scale };
    if (RELU) { a[0]=fmaxf(a[0],0.f); a[1]=fmaxf(a[1],0.f); a[2]=fmaxf(a[2],0.f); a[3]=fmaxf(a[3],0.f); }
    __nv_bfloat16 h[4], l[4];
    #pragma unroll
    for (int i = 0; i < 4; i++) hl_split(a[i], h[i], l[i]);
    __nv_bfloat16* oh = out + row * 1024 + threadIdx.x * 4;
    __nv_bfloat162 p;
    p.x=h[0]; p.y=h[1]; reinterpret_cast<__nv_bfloat162*>(oh)[0]=p;
    p.x=h[2]; p.y=h[3]; reinterpret_cast<__nv_bfloat162*>(oh)[1]=p;
    p.x=l[0]; p.y=l[1]; reinterpret_cast<__nv_bfloat162*>(oh+512)[0]=p;
    p.x=l[2]; p.y=l[3]; reinterpret_cast<__nv_bfloat162*>(oh+512)[1]=p;
}

// ---------------- DPB layer-0 -> bf16 [hi|lo] ----------------
__global__ __launch_bounds__(128) void dpb_in_kernel(const float* __restrict__ Wp,
                                                     const float* __restrict__ bp,
                                                     __nv_bfloat16* __restrict__ out)
{
    int m = blockIdx.x;
    float pp;
    if (m == 0 || m == 4096) pp = 0.f;
    else if (m < 4096)       pp = (float)m;
    else                     pp = (float)(m - 8192);
    float4 w = reinterpret_cast<const float4*>(Wp)[threadIdx.x];
    float4 b = reinterpret_cast<const float4*>(bp)[threadIdx.x];
    float a[4] = { fmaf(pp,w.x,b.x), fmaf(pp,w.y,b.y), fmaf(pp,w.z,b.z), fmaf(pp,w.w,b.w) };
    float s = a[0]*a[0]+a[1]*a[1]+a[2]*a[2]+a[3]*a[3];
    #pragma unroll
    for (int o = 16; o > 0; o >>= 1) s += __shfl_xor_sync(0xffffffffu, s, o);
    __shared__ float ws[4];
    if ((threadIdx.x & 31) == 0) ws[threadIdx.x >> 5] = s;
    __syncthreads();
    float tot = ws[0] + ws[1] + ws[2] + ws[3];
    float scale = 1.0f / (sqrtf(tot) * 0.04419417382415922f + 1e-8f);
    __nv_bfloat16 h[4], l[4];
    #pragma unroll
    for (int i = 0; i < 4; i++) hl_split(fmaxf(a[i]*scale, 0.f), h[i], l[i]);
    __nv_bfloat16* oh = out + (size_t)m * 1024 + threadIdx.x * 4;
    __nv_bfloat162 p;
    p.x=h[0]; p.y=h[1]; reinterpret_cast<__nv_bfloat162*>(oh)[0]=p;
    p.x=h[2]; p.y=h[3]; reinterpret_cast<__nv_bfloat162*>(oh)[1]=p;
    p.x=l[0]; p.y=l[1]; reinterpret_cast<__nv_bfloat162*>(oh+512)[0]=p;
    p.x=l[2]; p.y=l[3]; reinterpret_cast<__nv_bfloat162*>(oh+512)[1]=p;
}

// ---------------- weight split/transpose: W[K,N] fp32 -> [N, 3K] = [Bh|Bh|Bl] ----------------
__global__ void wsplit_kernel(const float* __restrict__ W, __nv_bfloat16* __restrict__ out,
                              int K, int N)
{
    __shared__ float t[32][33];
    int n0 = blockIdx.x * 32, k0 = blockIdx.y * 32;
    int tx = threadIdx.x, ty = threadIdx.y;
    #pragma unroll
    for (int j = 0; j < 32; j += 8)
        t[ty + j][tx] = W[(size_t)(k0 + ty + j) * N + n0 + tx];
    __syncthreads();
    #pragma unroll
    for (int j = 0; j < 32; j += 8) {
        int n = n0 + ty + j, k = k0 + tx;
        __nv_bfloat16 h, l; hl_split(t[tx][ty + j], h, l);
        size_t base = (size_t)n * 3 * K;
        out[base + k] = h; out[base + K + k] = h; out[base + 2*K + k] = l;
    }
}

// ---------------- mma.sync bf16 GEMM, 128x128 tile, 8 warps, K-chunks of 64 ----------------
// EPI: 0 plain f32 | 1 silu f32 | 2 gate*u -> bf16 hi/lo [M,2N] | 3 +res f32
#define GS   4
#define STB  32768                       // per-stage: 16KB A + 16KB B
#define DSM  (GS * STB + 1024)

template<int EPI>
__global__ __launch_bounds__(256) void mm_kernel(
    const __nv_bfloat16* __restrict__ A2, const __nv_bfloat16* __restrict__ B3,
    const float* __restrict__ bias, const float* __restrict__ gate,
    const float* __restrict__ res, float* __restrict__ Cf,
    __nv_bfloat16* __restrict__ Chl, int M, int N, int K)
{
    extern __shared__ char dsm[];
    int tid = threadIdx.x, lane = tid & 31, wid = tid >> 5;
    int wm = wid & 3, wn = wid >> 2;          // warp tile: rows wm*32, cols wn*64
    uint32_t raw = s2u(dsm);
    uint32_t dbase = (raw + 1023u) & ~1023u;

    int m0 = blockIdx.y * 128, n0 = blockIdx.x * 128;
    int nkk = K >> 6, nk = 3 * nkk;
    size_t rowA = (size_t)K * 4;   // bytes per A2 row (2K bf16)
    size_t rowB = (size_t)K * 6;   // bytes per B3 row (3K bf16)
    const char* Abase = (const char*)A2 + (size_t)m0 * rowA;
    const char* Bbase = (const char*)B3 + (size_t)n0 * rowB;

    auto load = [&](int c) {
        int s = c % GS;
        int ac = (c >= 2 * nkk) ? c - 2 * nkk : c;   // third pass re-reads Ah... no: c - 2nkk hits Al? layout [Ah|Al]: chunks 0..nkk-1 = Ah(Bh), nkk..2nkk-1 = Al(Bh), 2nkk.. = Ah(Bl)
        uint32_t sA = dbase + s * STB, sB = sA + 16384;
        const char* ga = Abase + (size_t)ac * 128;
        const char* gb = Bbase + (size_t)c * 128;
        #pragma unroll
        for (int i = 0; i < 4; i++) {
            int u = tid + i * 256; int r = u >> 3; int cc = (u & 7) * 16;
            cp16(sA + swz(r * 128 + cc), ga + (size_t)r * rowA + cc);
            cp16(sB + swz(r * 128 + cc), gb + (size_t)r * rowB + cc);
        }
        asm volatile("cp.async.commit_group;" ::: "memory");
    };
    // A chunk schedule: c in [0,nkk) -> Ah, [nkk,2nkk) -> Al, [2nkk,3nkk) -> Ah (re-read)
    // matches B [Bh|Bh|Bl]: sum = AhBh + AlBh + AhBl

    float acc[2][8][4];
    #pragma unroll
    for (int i = 0; i < 2; i++)
        #pragma unroll
        for (int j = 0; j < 8; j++)
            #pragma unroll
            for (int q = 0; q < 4; q++) acc[i][j][q] = 0.f;

    for (int i = 0; i < GS && i < nk; i++) load(i);

    for (int i = 0; i < nk; i++) {
        int s = i % GS;
        asm volatile("cp.async.wait_group %0;" :: "n"(GS - 1) : "memory");
        __syncthreads();
        uint32_t sA = dbase + s * STB, sB = sA + 16384;
        int t = lane >> 3, l7 = lane & 7;
        #pragma unroll
        for (int kk = 0; kk < 4; kk++) {
            int kb = kk * 16;
            uint32_t af[2][4], bf[4][4];
            #pragma unroll
            for (int im = 0; im < 2; im++) {
                int mrow = wm * 32 + im * 16 + ((t & 1) << 3) + l7;
                int kcol = kb + ((t >> 1) << 3);
                ldm4(af[im], sA + swz((uint32_t)(mrow * 128 + kcol * 2)));
            }
            #pragma unroll
            for (int jn = 0; jn < 4; jn++) {
                int nrow = wn * 64 + jn * 16 + ((t >> 1) << 3) + l7;
                int kcol = kb + ((t & 1) << 3);
                ldm4(bf[jn], sB + swz((uint32_t)(nrow * 128 + kcol * 2)));
            }
            #pragma unroll
            for (int im = 0; im < 2; im++)
                #pragma unroll
                for (int j = 0; j < 8; j++)
                    mmabf(acc[im][j], af[im], bf[j >> 1][(j & 1) * 2], bf[j >> 1][(j & 1) * 2 + 1]);
        }
        __syncthreads();
        if (i + GS < nk) load(i + GS);
    }

    // epilogue: fragment layout d0,d1 -> row lane/4, cols c,c+1 ; d2,d3 -> row+8
    #pragma unroll
    for (int im = 0; im < 2; im++) {
        #pragma unroll
        for (int j = 0; j < 8; j++) {
            int col = n0 + wn * 64 + j * 8 + (lane & 3) * 2;
            float b0 = bias[col], b1 = bias[col + 1];
            #pragma unroll
            for (int h = 0; h < 2; h++) {
                size_t row = (size_t)m0 + wm * 32 + im * 16 + (lane >> 2) + h * 8;
                size_t idx = row * (size_t)N + col;
                float v0 = acc[im][j][h * 2 + 0] + b0;
                float v1 = acc[im][j][h * 2 + 1] + b1;
                if (EPI == 1) { v0 = v0 / (1.f + __expf(-v0)); v1 = v1 / (1.f + __expf(-v1)); }
                if (EPI == 3) { v0 += res[idx]; v1 += res[idx + 1]; }
                if (EPI == 2) {
                    v0 *= gate[idx]; v1 *= gate[idx + 1];
                    __nv_bfloat16 h0, l0, h1, l1;
                    hl_split(v0, h0, l0); hl_split(v1, h1, l1);
                    __nv_bfloat162 ph; ph.x = h0; ph.y = h1;
                    __nv_bfloat162 pl; pl.x = l0; pl.y = l1;
                    *reinterpret_cast<__nv_bfloat162*>(Chl + row * (size_t)(2 * N) + col)     = ph;
                    *reinterpret_cast<__nv_bfloat162*>(Chl + row * (size_t)(2 * N) + N + col) = pl;
                } else {
                    float2 o; o.x = v0; o.y = v1;
                    *reinterpret_cast<float2*>(Cf + idx) = o;
                }
            }
        }
    }
}

// ---------------- 8192-pt radix-2 FFT (DIF fwd / DIT inv, bitrev spectra) ----------------
__device__ __forceinline__ void fft_fwd(float2* z, int tid)
{
    for (int s = 12; s >= 0; --s) {
        int len = 1 << s;
        for (int idx = tid; idx < 4096; idx += 512) {
            int j = idx & (len - 1);
            int i = ((idx >> s) << (s + 1)) + j;
            float2 u = z[i], w = z[i + len];
            z[i] = make_float2(u.x + w.x, u.y + w.y);
            float dx = u.x - w.x, dy = u.y - w.y;
            float sn, cs; __sincosf((-PI_F) * (float)j / (float)len, &sn, &cs);
            z[i + len] = make_float2(dx * cs - dy * sn, dx * sn + dy * cs);
        }
        __syncthreads();
    }
}
__device__ __forceinline__ void fft_inv(float2* z, int tid)
{
    for (int s = 0; s <= 12; ++s) {
        int len = 1 << s;
        for (int idx = tid; idx < 4096; idx += 512) {
            int j = idx & (len - 1);
            int i = ((idx >> s) << (s + 1)) + j;
            float sn, cs; __sincosf(PI_F * (float)j / (float)len, &sn, &cs);
            float2 u = z[i], w = z[i + len];
            float tx = w.x * cs - w.y * sn, ty = w.x * sn + w.y * cs;
            z[i]       = make_float2(u.x + tx, u.y + ty);
            z[i + len] = make_float2(u.x - tx, u.y - ty);
        }
        __syncthreads();
    }
}

__global__ __launch_bounds__(512) void af_kernel()
{
    extern __shared__ float2 z[];
    int c = blockIdx.x, tid = threadIdx.x;
    for (int m = tid; m < N_CIRC; m += 512)
        z[m] = make_float2(g_At[(size_t)m * DMODEL + c], 0.f);
    __syncthreads();
    fft_fwd(z, tid);
    const float inv = 1.0f / 8192.0f;
    for (int k = tid; k < N_CIRC; k += 512) {
        float2 v = z[k];
        g_Af[(size_t)c * N_CIRC + k] = make_float2(v.x * inv, v.y * inv);
    }
}

__global__ __launch_bounds__(512) void conv_kernel()
{
    extern __shared__ float2 z[];
    int b = blockIdx.x >> 9, c = blockIdx.x & 511, tid = threadIdx.x;
    const float* vp = g_v + ((size_t)b * N_SEQ) * DMODEL + c;
    for (int j = tid; j < N_SEQ; j += 512)
        z[j] = make_float2(vp[(size_t)j * DMODEL], 0.f);
    for (int j = N_SEQ + tid; j < N_CIRC; j += 512)
        z[j] = make_float2(0.f, 0.f);
    __syncthreads();
    fft_fwd(z, tid);
    const float2* af = g_Af + (size_t)c * N_CIRC;
    for (int k = tid; k < N_CIRC; k += 512) {
        float2 a = af[k], v = z[k];
        z[k] = make_float2(v.x * a.x - v.y * a.y, v.x * a.y + v.y * a.x);
    }
    __syncthreads();
    fft_inv(z, tid);
    size_t rbase = ((size_t)b * N_SEQ) * 1024;
    for (int i = tid; i < N_SEQ; i += 512) {
        __nv_bfloat16 h, l; hl_split(z[i].x, h, l);
        g_conv2[rbase + (size_t)i * 1024 + c]       = h;
        g_conv2[rbase + (size_t)i * 1024 + 512 + c] = l;
    }
}

// ---------------- host ----------------
static float* sym_f(const void* s) { void* p = nullptr; cudaGetSymbolAddress(&p, s); return (float*)p; }
static __nv_bfloat16* sym_h(const void* s) { void* p = nullptr; cudaGetSymbolAddress(&p, s); return (__nv_bfloat16*)p; }

extern "C" void kernel_launch(void* const* d_in, const int* in_sizes, int n_in,
                              void* d_out, int out_size)
{
    const float* x   = (const float*)d_in[0];
    const float* Wu  = (const float*)d_in[1];  const float* bu  = (const float*)d_in[2];
    const float* Wv  = (const float*)d_in[3];  const float* bv  = (const float*)d_in[4];
    const float* Wo1 = (const float*)d_in[5];  const float* bo1 = (const float*)d_in[6];
    const float* Wo2 = (const float*)d_in[7];  const float* bo2 = (const float*)d_in[8];
    const float* dWp = (const float*)d_in[9];  const float* dbp = (const float*)d_in[10];
    const float* dW1 = (const float*)d_in[11]; const float* db1 = (const float*)d_in[12];
    const float* dW2 = (const float*)d_in[13]; const float* db2 = (const float*)d_in[14];
    const float* dW3 = (const float*)d_in[15]; const float* db3 = (const float*)d_in[16];
    float* out = (float*)d_out;

    cudaFuncSetAttribute(af_kernel,    cudaFuncAttributeMaxDynamicSharedMemorySize, 65536);
    cudaFuncSetAttribute(conv_kernel,  cudaFuncAttributeMaxDynamicSharedMemorySize, 65536);
    cudaFuncSetAttribute(mm_kernel<0>, cudaFuncAttributeMaxDynamicSharedMemorySize, DSM);
    cudaFuncSetAttribute(mm_kernel<1>, cudaFuncAttributeMaxDynamicSharedMemorySize, DSM);
    cudaFuncSetAttribute(mm_kernel<2>, cudaFuncAttributeMaxDynamicSharedMemorySize, DSM);
    cudaFuncSetAttribute(mm_kernel<3>, cudaFuncAttributeMaxDynamicSharedMemorySize, DSM);

    float* p_u  = sym_f(g_u);   float* p_v  = sym_f(g_v);
    float* p_tb = sym_f(g_tb);  float* p_At = sym_f(g_At);
    __nv_bfloat16* p_xn2  = sym_h(g_xn2);   __nv_bfloat16* p_ta2  = sym_h(g_ta2);
    __nv_bfloat16* p_cv2  = sym_h(g_conv2); __nv_bfloat16* p_gt2  = sym_h(g_gate2);
    __nv_bfloat16* p_Wu3  = sym_h(g_Wu3);   __nv_bfloat16* p_Wv3  = sym_h(g_Wv3);
    __nv_bfloat16* p_Wo13 = sym_h(g_Wo13);  __nv_bfloat16* p_Wo23 = sym_h(g_Wo23);
    __nv_bfloat16* p_dW13 = sym_h(g_dW13);  __nv_bfloat16* p_dW23 = sym_h(g_dW23);
    __nv_bfloat16* p_dW33 = sym_h(g_dW33);

    dim3 wb(32, 8);
    wsplit_kernel<<<dim3(1024/32, 512/32),  wb>>>(Wu,  p_Wu3,  512, 1024);
    wsplit_kernel<<<dim3(512/32,  512/32),  wb>>>(Wv,  p_Wv3,  512, 512);
    wsplit_kernel<<<dim3(1024/32, 512/32),  wb>>>(Wo1, p_Wo13, 512, 1024);
    wsplit_kernel<<<dim3(512/32,  1024/32), wb>>>(Wo2, p_Wo23, 1024, 512);
    wsplit_kernel<<<dim3(512/32,  512/32),  wb>>>(dW1, p_dW13, 512, 512);
    wsplit_kernel<<<dim3(512/32,  512/32),  wb>>>(dW2, p_dW23, 512, 512);
    wsplit_kernel<<<dim3(512/32,  512/32),  wb>>>(dW3, p_dW33, 512, 512);

    // pre-norm -> bf16 hi/lo
    srms_hl_kernel<0><<<NROWS, 128>>>(x, p_xn2);
    // u, v projections
    mm_kernel<1><<<dim3(8, 256), 256, DSM>>>(p_xn2, p_Wu3, bu, nullptr, nullptr, p_u, nullptr, NROWS, 1024, 512);
    mm_kernel<1><<<dim3(4, 256), 256, DSM>>>(p_xn2, p_Wv3, bv, nullptr, nullptr, p_v, nullptr, NROWS, 512, 512);
    // DPB MLP
    dpb_in_kernel<<<N_CIRC, 128>>>(dWp, dbp, p_ta2);
    mm_kernel<0><<<dim3(4, 64), 256, DSM>>>(p_ta2, p_dW13, db1, nullptr, nullptr, p_tb, nullptr, N_CIRC, 512, 512);
    srms_hl_kernel<1><<<N_CIRC, 128>>>(p_tb, p_ta2);
    mm_kernel<0><<<dim3(4, 64), 256, DSM>>>(p_ta2, p_dW23, db2, nullptr, nullptr, p_tb, nullptr, N_CIRC, 512, 512);
    srms_hl_kernel<1><<<N_CIRC, 128>>>(p_tb, p_ta2);
    mm_kernel<0><<<dim3(4, 64), 256, DSM>>>(p_ta2, p_dW33, db3, nullptr, nullptr, p_At, nullptr, N_CIRC, 512, 512);
    // spectra + convolution
    af_kernel<<<512, 512, 65536>>>();
    conv_kernel<<<NROWS / 8, 512, 65536>>>();
    // gated output projections + residual
    mm_kernel<2><<<dim3(8, 256), 256, DSM>>>(p_cv2, p_Wo13, bo1, p_u, nullptr, nullptr, p_gt2, NROWS, 1024, 512);
    mm_kernel<3><<<dim3(4, 256), 256, DSM>>>(p_gt2, p_Wo23, bo2, nullptr, x, out, nullptr, NROWS, 512, 1024);
}

// round 15
// speedup vs baseline: 1.8025x; 1.0188x over previous
#include <cuda_runtime.h>
#include <cuda_bf16.h>
#include <cstdint>

#define PI_F 3.14159265358979323846f
#define N_SEQ   4096
#define N_CIRC  8192
#define DMODEL  512
#define NROWS   32768

// ---------------- scratch ----------------
__device__ float  g_u   [(size_t)NROWS * 1024];
__device__ float  g_v   [(size_t)NROWS * 512];
__device__ float  g_tb  [(size_t)N_CIRC * 512];
__device__ float  g_At  [(size_t)N_CIRC * 512];
__device__ float2 g_Af  [(size_t)512 * N_CIRC];
__device__ __nv_bfloat16 g_xn2  [(size_t)NROWS * 1024];
__device__ __nv_bfloat16 g_ta2  [(size_t)N_CIRC * 1024];
__device__ __nv_bfloat16 g_conv2[(size_t)NROWS * 1024];
__device__ __nv_bfloat16 g_gate2[(size_t)NROWS * 2048];
__device__ __nv_bfloat16 g_Wu3 [(size_t)1024 * 1536];
__device__ __nv_bfloat16 g_Wv3 [(size_t)512  * 1536];
__device__ __nv_bfloat16 g_Wo13[(size_t)1024 * 1536];
__device__ __nv_bfloat16 g_Wo23[(size_t)512  * 3072];
__device__ __nv_bfloat16 g_dW13[(size_t)512  * 1536];
__device__ __nv_bfloat16 g_dW23[(size_t)512  * 1536];
__device__ __nv_bfloat16 g_dW33[(size_t)512  * 1536];

// ---------------- helpers ----------------
__device__ __forceinline__ uint32_t s2u(const void* p){ return (uint32_t)__cvta_generic_to_shared(p); }
__device__ __forceinline__ uint32_t swz(uint32_t o){ return o ^ ((o >> 3) & 0x70); }
__device__ __forceinline__ void cp16(uint32_t d, const void* g){
    asm volatile("cp.async.cg.shared.global [%0], [%1], 16;" :: "r"(d), "l"(g));
}
__device__ __forceinline__ void hl_split(float x, __nv_bfloat16& h, __nv_bfloat16& l){
    h = __float2bfloat16(x);
    l = __float2bfloat16(x - __bfloat162float(h));
}
__device__ __forceinline__ void ldm4(uint32_t* r, uint32_t a){
    asm volatile("ldmatrix.sync.aligned.m8n8.x4.shared.b16 {%0,%1,%2,%3}, [%4];"
        : "=r"(r[0]),"=r"(r[1]),"=r"(r[2]),"=r"(r[3]) : "r"(a));
}
__device__ __forceinline__ void mmabf(float* d, const uint32_t* a, uint32_t b0, uint32_t b1){
    asm volatile("mma.sync.aligned.m16n8k16.row.col.f32.bf16.bf16.f32 "
        "{%0,%1,%2,%3}, {%4,%5,%6,%7}, {%8,%9}, {%0,%1,%2,%3};"
        : "+f"(d[0]),"+f"(d[1]),"+f"(d[2]),"+f"(d[3])
        : "r"(a[0]),"r"(a[1]),"r"(a[2]),"r"(a[3]), "r"(b0),"r"(b1));
}

// ---------------- SimpleRMSNorm(+ReLU) -> bf16 [hi|lo] ----------------
template<int RELU>
__global__ __launch_bounds__(128) void srms_hl_kernel(const float* __restrict__ in,
                                                      __nv_bfloat16* __restrict__ out)
{
    size_t row = blockIdx.x;
    float4 v = reinterpret_cast<const float4*>(in + row * DMODEL)[threadIdx.x];
    float s = v.x*v.x + v.y*v.y + v.z*v.z + v.w*v.w;
    #pragma unroll
    for (int o = 16; o > 0; o >>= 1) s += __shfl_xor_sync(0xffffffffu, s, o);
    __shared__ float ws[4];
    if ((threadIdx.x & 31) == 0) ws[threadIdx.x >> 5] = s;
    __syncthreads();
    float tot = ws[0] + ws[1] + ws[2] + ws[3];
    float scale = 1.0f / (sqrtf(tot) * 0.04419417382415922f + 1e-8f);
    float a[4] = { v.x*scale, v.y*scale, v.z*scale, v.w*scale };
    if (RELU) { a[0]=fmaxf(a[0],0.f); a[1]=fmaxf(a[1],0.f); a[2]=fmaxf(a[2],0.f); a[3]=fmaxf(a[3],0.f); }
    __nv_bfloat16 h[4], l[4];
    #pragma unroll
    for (int i = 0; i < 4; i++) hl_split(a[i], h[i], l[i]);
    __nv_bfloat16* oh = out + row * 1024 + threadIdx.x * 4;
    __nv_bfloat162 p;
    p.x=h[0]; p.y=h[1]; reinterpret_cast<__nv_bfloat162*>(oh)[0]=p;
    p.x=h[2]; p.y=h[3]; reinterpret_cast<__nv_bfloat162*>(oh)[1]=p;
    p.x=l[0]; p.y=l[1]; reinterpret_cast<__nv_bfloat162*>(oh+512)[0]=p;
    p.x=l[2]; p.y=l[3]; reinterpret_cast<__nv_bfloat162*>(oh+512)[1]=p;
}

// ---------------- DPB layer-0 -> bf16 [hi|lo] ----------------
__global__ __launch_bounds__(128) void dpb_in_kernel(const float* __restrict__ Wp,
                                                     const float* __restrict__ bp,
                                                     __nv_bfloat16* __restrict__ out)
{
    int m = blockIdx.x;
    float pp;
    if (m == 0 || m == 4096) pp = 0.f;
    else if (m < 4096)       pp = (float)m;
    else                     pp = (float)(m - 8192);
    float4 w = reinterpret_cast<const float4*>(Wp)[threadIdx.x];
    float4 b = reinterpret_cast<const float4*>(bp)[threadIdx.x];
    float a[4] = { fmaf(pp,w.x,b.x), fmaf(pp,w.y,b.y), fmaf(pp,w.z,b.z), fmaf(pp,w.w,b.w) };
    float s = a[0]*a[0]+a[1]*a[1]+a[2]*a[2]+a[3]*a[3];
    #pragma unroll
    for (int o = 16; o > 0; o >>= 1) s += __shfl_xor_sync(0xffffffffu, s, o);
    __shared__ float ws[4];
    if ((threadIdx.x & 31) == 0) ws[threadIdx.x >> 5] = s;
    __syncthreads();
    float tot = ws[0] + ws[1] + ws[2] + ws[3];
    float scale = 1.0f / (sqrtf(tot) * 0.04419417382415922f + 1e-8f);
    __nv_bfloat16 h[4], l[4];
    #pragma unroll
    for (int i = 0; i < 4; i++) hl_split(fmaxf(a[i]*scale, 0.f), h[i], l[i]);
    __nv_bfloat16* oh = out + (size_t)m * 1024 + threadIdx.x * 4;
    __nv_bfloat162 p;
    p.x=h[0]; p.y=h[1]; reinterpret_cast<__nv_bfloat162*>(oh)[0]=p;
    p.x=h[2]; p.y=h[3]; reinterpret_cast<__nv_bfloat162*>(oh)[1]=p;
    p.x=l[0]; p.y=l[1]; reinterpret_cast<__nv_bfloat162*>(oh+512)[0]=p;
    p.x=l[2]; p.y=l[3]; reinterpret_cast<__nv_bfloat162*>(oh+512)[1]=p;
}

// ---------------- weight split/transpose: W[K,N] fp32 -> [N, 3K] = [Bh|Bh|Bl] ----------------
__global__ void wsplit_kernel(const float* __restrict__ W, __nv_bfloat16* __restrict__ out,
                              int K, int N)
{
    __shared__ float t[32][33];
    int n0 = blockIdx.x * 32, k0 = blockIdx.y * 32;
    int tx = threadIdx.x, ty = threadIdx.y;
    #pragma unroll
    for (int j = 0; j < 32; j += 8)
        t[ty + j][tx] = W[(size_t)(k0 + ty + j) * N + n0 + tx];
    __syncthreads();
    #pragma unroll
    for (int j = 0; j < 32; j += 8) {
        int n = n0 + ty + j, k = k0 + tx;
        __nv_bfloat16 h, l; hl_split(t[tx][ty + j], h, l);
        size_t base = (size_t)n * 3 * K;
        out[base + k] = h; out[base + K + k] = h; out[base + 2*K + k] = l;
    }
}

// ---------------- mma.sync bf16 GEMM, 128x256 CTA tile, 8 warps @ 64x64 ----------------
// EPI: 0 plain f32 | 1 silu f32 | 2 gate*u -> bf16 hi/lo [M,2N] | 3 +res f32
#define GS   3
#define STB  49152                       // per-stage: 16KB A + 32KB B
#define DSM  (GS * STB + 1024)

template<int EPI>
__global__ __launch_bounds__(256, 1) void mm_kernel(
    const __nv_bfloat16* __restrict__ A2, const __nv_bfloat16* __restrict__ B3,
    const float* __restrict__ bias, const float* __restrict__ gate,
    const float* __restrict__ res, float* __restrict__ Cf,
    __nv_bfloat16* __restrict__ Chl, int M, int N, int K)
{
    extern __shared__ char dsm[];
    int tid = threadIdx.x, lane = tid & 31, wid = tid >> 5;
    int wm = wid & 1, wn = wid >> 1;          // warp tile: rows wm*64, cols wn*64
    uint32_t raw = s2u(dsm);
    uint32_t dbase = (raw + 1023u) & ~1023u;

    int m0 = blockIdx.y * 128, n0 = blockIdx.x * 256;
    int nkk = K >> 6, nk = 3 * nkk;
    size_t rowA = (size_t)K * 4;   // bytes per A2 row (2K bf16)
    size_t rowB = (size_t)K * 6;   // bytes per B3 row (3K bf16)
    const char* Abase = (const char*)A2 + (size_t)m0 * rowA;
    const char* Bbase = (const char*)B3 + (size_t)n0 * rowB;

    // chunk schedule: c in [0,nkk) -> Ah*Bh, [nkk,2nkk) -> Al*Bh, [2nkk,3nkk) -> Ah*Bl
    auto load = [&](int c) {
        int s = c % GS;
        int ac = (c >= 2 * nkk) ? c - 2 * nkk : c;
        uint32_t sA = dbase + s * STB, sB = sA + 16384;
        const char* ga = Abase + (size_t)ac * 128;
        const char* gb = Bbase + (size_t)c * 128;
        #pragma unroll
        for (int i = 0; i < 4; i++) {
            int u = tid + i * 256; int r = u >> 3; int cc = (u & 7) * 16;
            cp16(sA + swz(r * 128 + cc), ga + (size_t)r * rowA + cc);
        }
        #pragma unroll
        for (int i = 0; i < 8; i++) {
            int u = tid + i * 256; int r = u >> 3; int cc = (u & 7) * 16;
            cp16(sB + swz(r * 128 + cc), gb + (size_t)r * rowB + cc);
        }
        asm volatile("cp.async.commit_group;" ::: "memory");
    };

    float acc[4][8][4];
    #pragma unroll
    for (int i = 0; i < 4; i++)
        #pragma unroll
        for (int j = 0; j < 8; j++)
            #pragma unroll
            for (int q = 0; q < 4; q++) acc[i][j][q] = 0.f;

    for (int i = 0; i < GS && i < nk; i++) load(i);

    for (int i = 0; i < nk; i++) {
        int s = i % GS;
        asm volatile("cp.async.wait_group %0;" :: "n"(GS - 1) : "memory");
        __syncthreads();
        uint32_t sA = dbase + s * STB, sB = sA + 16384;
        int t = lane >> 3, l7 = lane & 7;
        #pragma unroll
        for (int kk = 0; kk < 4; kk++) {
            int kb = kk * 16;
            uint32_t af[4][4], bf[4][4];
            #pragma unroll
            for (int im = 0; im < 4; im++) {
                int mrow = wm * 64 + im * 16 + ((t & 1) << 3) + l7;
                int kcol = kb + ((t >> 1) << 3);
                ldm4(af[im], sA + swz((uint32_t)(mrow * 128 + kcol * 2)));
            }
            #pragma unroll
            for (int jn = 0; jn < 4; jn++) {
                int nrow = wn * 64 + jn * 16 + ((t >> 1) << 3) + l7;
                int kcol = kb + ((t & 1) << 3);
                ldm4(bf[jn], sB + swz((uint32_t)(nrow * 128 + kcol * 2)));
            }
            #pragma unroll
            for (int im = 0; im < 4; im++)
                #pragma unroll
                for (int j = 0; j < 8; j++)
                    mmabf(acc[im][j], af[im], bf[j >> 1][(j & 1) * 2], bf[j >> 1][(j & 1) * 2 + 1]);
        }
        __syncthreads();
        if (i + GS < nk) load(i + GS);
    }

    // epilogue: d0,d1 -> row lane/4, cols c,c+1 ; d2,d3 -> row+8
    #pragma unroll
    for (int im = 0; im < 4; im++) {
        #pragma unroll
        for (int j = 0; j < 8; j++) {
            int col = n0 + wn * 64 + j * 8 + (lane & 3) * 2;
            float b0 = bias[col], b1 = bias[col + 1];
            #pragma unroll
            for (int h = 0; h < 2; h++) {
                size_t row = (size_t)m0 + wm * 64 + im * 16 + (lane >> 2) + h * 8;
                size_t idx = row * (size_t)N + col;
                float v0 = acc[im][j][h * 2 + 0] + b0;
                float v1 = acc[im][j][h * 2 + 1] + b1;
                if (EPI == 1) { v0 = v0 / (1.f + __expf(-v0)); v1 = v1 / (1.f + __expf(-v1)); }
                if (EPI == 3) { v0 += res[idx]; v1 += res[idx + 1]; }
                if (EPI == 2) {
                    v0 *= gate[idx]; v1 *= gate[idx + 1];
                    __nv_bfloat16 h0, l0, h1, l1;
                    hl_split(v0, h0, l0); hl_split(v1, h1, l1);
                    __nv_bfloat162 ph; ph.x = h0; ph.y = h1;
                    __nv_bfloat162 pl; pl.x = l0; pl.y = l1;
                    *reinterpret_cast<__nv_bfloat162*>(Chl + row * (size_t)(2 * N) + col)     = ph;
                    *reinterpret_cast<__nv_bfloat162*>(Chl + row * (size_t)(2 * N) + N + col) = pl;
                } else {
                    float2 o; o.x = v0; o.y = v1;
                    *reinterpret_cast<float2*>(Cf + idx) = o;
                }
            }
        }
    }
}

// ---------------- 8192-pt radix-2 FFT (DIF fwd / DIT inv, bitrev spectra) ----------------
__device__ __forceinline__ void fft_fwd(float2* z, int tid)
{
    for (int s = 12; s >= 0; --s) {
        int len = 1 << s;
        for (int idx = tid; idx < 4096; idx += 512) {
            int j = idx & (len - 1);
            int i = ((idx >> s) << (s + 1)) + j;
            float2 u = z[i], w = z[i + len];
            z[i] = make_float2(u.x + w.x, u.y + w.y);
            float dx = u.x - w.x, dy = u.y - w.y;
            float sn, cs; __sincosf((-PI_F) * (float)j / (float)len, &sn, &cs);
            z[i + len] = make_float2(dx * cs - dy * sn, dx * sn + dy * cs);
        }
        __syncthreads();
    }
}
__device__ __forceinline__ void fft_inv(float2* z, int tid)
{
    for (int s = 0; s <= 12; ++s) {
        int len = 1 << s;
        for (int idx = tid; idx < 4096; idx += 512) {
            int j = idx & (len - 1);
            int i = ((idx >> s) << (s + 1)) + j;
            float sn, cs; __sincosf(PI_F * (float)j / (float)len, &sn, &cs);
            float2 u = z[i], w = z[i + len];
            float tx = w.x * cs - w.y * sn, ty = w.x * sn + w.y * cs;
            z[i]       = make_float2(u.x + tx, u.y + ty);
            z[i + len] = make_float2(u.x - tx, u.y - ty);
        }
        __syncthreads();
    }
}

__global__ __launch_bounds__(512) void af_kernel()
{
    extern __shared__ float2 z[];
    int c = blockIdx.x, tid = threadIdx.x;
    for (int m = tid; m < N_CIRC; m += 512)
        z[m] = make_float2(g_At[(size_t)m * DMODEL + c], 0.f);
    __syncthreads();
    fft_fwd(z, tid);
    const float inv = 1.0f / 8192.0f;
    for (int k = tid; k < N_CIRC; k += 512) {
        float2 v = z[k];
        g_Af[(size_t)c * N_CIRC + k] = make_float2(v.x * inv, v.y * inv);
    }
}

__global__ __launch_bounds__(512) void conv_kernel()
{
    extern __shared__ float2 z[];
    int b = blockIdx.x >> 9, c = blockIdx.x & 511, tid = threadIdx.x;
    const float* vp = g_v + ((size_t)b * N_SEQ) * DMODEL + c;
    for (int j = tid; j < N_SEQ; j += 512)
        z[j] = make_float2(vp[(size_t)j * DMODEL], 0.f);
    for (int j = N_SEQ + tid; j < N_CIRC; j += 512)
        z[j] = make_float2(0.f, 0.f);
    __syncthreads();
    fft_fwd(z, tid);
    const float2* af = g_Af + (size_t)c * N_CIRC;
    for (int k = tid; k < N_CIRC; k += 512) {
        float2 a = af[k], v = z[k];
        z[k] = make_float2(v.x * a.x - v.y * a.y, v.x * a.y + v.y * a.x);
    }
    __syncthreads();
    fft_inv(z, tid);
    size_t rbase = ((size_t)b * N_SEQ) * 1024;
    for (int i = tid; i < N_SEQ; i += 512) {
        __nv_bfloat16 h, l; hl_split(z[i].x, h, l);
        g_conv2[rbase + (size_t)i * 1024 + c]       = h;
        g_conv2[rbase + (size_t)i * 1024 + 512 + c] = l;
    }
}

// ---------------- host ----------------
static float* sym_f(const void* s) { void* p = nullptr; cudaGetSymbolAddress(&p, s); return (float*)p; }
static __nv_bfloat16* sym_h(const void* s) { void* p = nullptr; cudaGetSymbolAddress(&p, s); return (__nv_bfloat16*)p; }

extern "C" void kernel_launch(void* const* d_in, const int* in_sizes, int n_in,
                              void* d_out, int out_size)
{
    const float* x   = (const float*)d_in[0];
    const float* Wu  = (const float*)d_in[1];  const float* bu  = (const float*)d_in[2];
    const float* Wv  = (const float*)d_in[3];  const float* bv  = (const float*)d_in[4];
    const float* Wo1 = (const float*)d_in[5];  const float* bo1 = (const float*)d_in[6];
    const float* Wo2 = (const float*)d_in[7];  const float* bo2 = (const float*)d_in[8];
    const float* dWp = (const float*)d_in[9];  const float* dbp = (const float*)d_in[10];
    const float* dW1 = (const float*)d_in[11]; const float* db1 = (const float*)d_in[12];
    const float* dW2 = (const float*)d_in[13]; const float* db2 = (const float*)d_in[14];
    const float* dW3 = (const float*)d_in[15]; const float* db3 = (const float*)d_in[16];
    float* out = (float*)d_out;

    cudaFuncSetAttribute(af_kernel,    cudaFuncAttributeMaxDynamicSharedMemorySize, 65536);
    cudaFuncSetAttribute(conv_kernel,  cudaFuncAttributeMaxDynamicSharedMemorySize, 65536);
    cudaFuncSetAttribute(mm_kernel<0>, cudaFuncAttributeMaxDynamicSharedMemorySize, DSM);
    cudaFuncSetAttribute(mm_kernel<1>, cudaFuncAttributeMaxDynamicSharedMemorySize, DSM);
    cudaFuncSetAttribute(mm_kernel<2>, cudaFuncAttributeMaxDynamicSharedMemorySize, DSM);
    cudaFuncSetAttribute(mm_kernel<3>, cudaFuncAttributeMaxDynamicSharedMemorySize, DSM);

    float* p_u  = sym_f(g_u);   float* p_v  = sym_f(g_v);
    float* p_tb = sym_f(g_tb);  float* p_At = sym_f(g_At);
    __nv_bfloat16* p_xn2  = sym_h(g_xn2);   __nv_bfloat16* p_ta2  = sym_h(g_ta2);
    __nv_bfloat16* p_cv2  = sym_h(g_conv2); __nv_bfloat16* p_gt2  = sym_h(g_gate2);
    __nv_bfloat16* p_Wu3  = sym_h(g_Wu3);   __nv_bfloat16* p_Wv3  = sym_h(g_Wv3);
    __nv_bfloat16* p_Wo13 = sym_h(g_Wo13);  __nv_bfloat16* p_Wo23 = sym_h(g_Wo23);
    __nv_bfloat16* p_dW13 = sym_h(g_dW13);  __nv_bfloat16* p_dW23 = sym_h(g_dW23);
    __nv_bfloat16* p_dW33 = sym_h(g_dW33);

    dim3 wb(32, 8);
    wsplit_kernel<<<dim3(1024/32, 512/32),  wb>>>(Wu,  p_Wu3,  512, 1024);
    wsplit_kernel<<<dim3(512/32,  512/32),  wb>>>(Wv,  p_Wv3,  512, 512);
    wsplit_kernel<<<dim3(1024/32, 512/32),  wb>>>(Wo1, p_Wo13, 512, 1024);
    wsplit_kernel<<<dim3(512/32,  1024/32), wb>>>(Wo2, p_Wo23, 1024, 512);
    wsplit_kernel<<<dim3(512/32,  512/32),  wb>>>(dW1, p_dW13, 512, 512);
    wsplit_kernel<<<dim3(512/32,  512/32),  wb>>>(dW2, p_dW23, 512, 512);
    wsplit_kernel<<<dim3(512/32,  512/32),  wb>>>(dW3, p_dW33, 512, 512);

    // pre-norm -> bf16 hi/lo
    srms_hl_kernel<0><<<NROWS, 128>>>(x, p_xn2);
    // u, v projections
    mm_kernel<1><<<dim3(4, 256), 256, DSM>>>(p_xn2, p_Wu3, bu, nullptr, nullptr, p_u, nullptr, NROWS, 1024, 512);
    mm_kernel<1><<<dim3(2, 256), 256, DSM>>>(p_xn2, p_Wv3, bv, nullptr, nullptr, p_v, nullptr, NROWS, 512, 512);
    // DPB MLP
    dpb_in_kernel<<<N_CIRC, 128>>>(dWp, dbp, p_ta2);
    mm_kernel<0><<<dim3(2, 64), 256, DSM>>>(p_ta2, p_dW13, db1, nullptr, nullptr, p_tb, nullptr, N_CIRC, 512, 512);
    srms_hl_kernel<1><<<N_CIRC, 128>>>(p_tb, p_ta2);
    mm_kernel<0><<<dim3(2, 64), 256, DSM>>>(p_ta2, p_dW23, db2, nullptr, nullptr, p_tb, nullptr, N_CIRC, 512, 512);
    srms_hl_kernel<1><<<N_CIRC, 128>>>(p_tb, p_ta2);
    mm_kernel<0><<<dim3(2, 64), 256, DSM>>>(p_ta2, p_dW33, db3, nullptr, nullptr, p_At, nullptr, N_CIRC, 512, 512);
    // spectra + convolution
    af_kernel<<<512, 512, 65536>>>();
    conv_kernel<<<NROWS / 8, 512, 65536>>>();
    // gated output projections + residual
    mm_kernel<2><<<dim3(4, 256), 256, DSM>>>(p_cv2, p_Wo13, bo1, p_u, nullptr, nullptr, p_gt2, NROWS, 1024, 512);
    mm_kernel<3><<<dim3(2, 256), 256, DSM>>>(p_gt2, p_Wo23, bo2, nullptr, x, out, nullptr, NROWS, 512, 1024);
}

// round 17
// speedup vs baseline: 2.1889x; 1.2144x over previous
#include <cuda_runtime.h>
#include <cuda_bf16.h>
#include <cstdint>

#define PI_F 3.14159265358979323846f
#define N_SEQ   4096
#define N_CIRC  8192
#define DMODEL  512
#define NROWS   32768

// ---------------- scratch ----------------
__device__ float  g_u   [(size_t)NROWS * 1024];
__device__ float  g_v   [(size_t)NROWS * 512];
__device__ float  g_vT  [(size_t)NROWS * 512];     // [b][c][i]
__device__ float  g_cT  [(size_t)NROWS * 512];     // conv result [b][c][i]
__device__ float  g_tb  [(size_t)N_CIRC * 512];
__device__ float  g_At  [(size_t)N_CIRC * 512];
__device__ float2 g_Af  [(size_t)512 * N_CIRC];
__device__ __nv_bfloat16 g_xn2  [(size_t)NROWS * 1024];
__device__ __nv_bfloat16 g_ta2  [(size_t)N_CIRC * 1024];
__device__ __nv_bfloat16 g_conv2[(size_t)NROWS * 1024];
__device__ __nv_bfloat16 g_gate2[(size_t)NROWS * 2048];
__device__ __nv_bfloat16 g_Wu3 [(size_t)1024 * 1536];
__device__ __nv_bfloat16 g_Wv3 [(size_t)512  * 1536];
__device__ __nv_bfloat16 g_Wo13[(size_t)1024 * 1536];
__device__ __nv_bfloat16 g_Wo23[(size_t)512  * 3072];
__device__ __nv_bfloat16 g_dW13[(size_t)512  * 1536];
__device__ __nv_bfloat16 g_dW23[(size_t)512  * 1536];
__device__ __nv_bfloat16 g_dW33[(size_t)512  * 1536];

// ---------------- helpers ----------------
__device__ __forceinline__ uint32_t s2u(const void* p){ return (uint32_t)__cvta_generic_to_shared(p); }
__device__ __forceinline__ uint32_t swz(uint32_t o){ return o ^ ((o >> 3) & 0x70); }
__device__ __forceinline__ void cp16(uint32_t d, const void* g){
    asm volatile("cp.async.cg.shared.global [%0], [%1], 16;" :: "r"(d), "l"(g));
}
__device__ __forceinline__ void hl_split(float x, __nv_bfloat16& h, __nv_bfloat16& l){
    h = __float2bfloat16(x);
    l = __float2bfloat16(x - __bfloat162float(h));
}
__device__ __forceinline__ void ldm4(uint32_t* r, uint32_t a){
    asm volatile("ldmatrix.sync.aligned.m8n8.x4.shared.b16 {%0,%1,%2,%3}, [%4];"
        : "=r"(r[0]),"=r"(r[1]),"=r"(r[2]),"=r"(r[3]) : "r"(a));
}
__device__ __forceinline__ void mmabf(float* d, const uint32_t* a, uint32_t b0, uint32_t b1){
    asm volatile("mma.sync.aligned.m16n8k16.row.col.f32.bf16.bf16.f32 "
        "{%0,%1,%2,%3}, {%4,%5,%6,%7}, {%8,%9}, {%0,%1,%2,%3};"
        : "+f"(d[0]),"+f"(d[1]),"+f"(d[2]),"+f"(d[3])
        : "r"(a[0]),"r"(a[1]),"r"(a[2]),"r"(a[3]), "r"(b0),"r"(b1));
}

// ---------------- SimpleRMSNorm(+ReLU) -> bf16 [hi|lo] ----------------
template<int RELU>
__global__ __launch_bounds__(128) void srms_hl_kernel(const float* __restrict__ in,
                                                      __nv_bfloat16* __restrict__ out)
{
    size_t row = blockIdx.x;
    float4 v = reinterpret_cast<const float4*>(in + row * DMODEL)[threadIdx.x];
    float s = v.x*v.x + v.y*v.y + v.z*v.z + v.w*v.w;
    #pragma unroll
    for (int o = 16; o > 0; o >>= 1) s += __shfl_xor_sync(0xffffffffu, s, o);
    __shared__ float ws[4];
    if ((threadIdx.x & 31) == 0) ws[threadIdx.x >> 5] = s;
    __syncthreads();
    float tot = ws[0] + ws[1] + ws[2] + ws[3];
    float scale = 1.0f / (sqrtf(tot) * 0.04419417382415922f + 1e-8f);
    float a[4] = { v.x*scale, v.y*scale, v.z*scale, v.w*scale };
    if (RELU) { a[0]=fmaxf(a[0],0.f); a[1]=fmaxf(a[1],0.f); a[2]=fmaxf(a[2],0.f); a[3]=fmaxf(a[3],0.f); }
    __nv_bfloat16 h[4], l[4];
    #pragma unroll
    for (int i = 0; i < 4; i++) hl_split(a[i], h[i], l[i]);
    __nv_bfloat16* oh = out + row * 1024 + threadIdx.x * 4;
    __nv_bfloat162 p;
    p.x=h[0]; p.y=h[1]; reinterpret_cast<__nv_bfloat162*>(oh)[0]=p;
    p.x=h[2]; p.y=h[3]; reinterpret_cast<__nv_bfloat162*>(oh)[1]=p;
    p.x=l[0]; p.y=l[1]; reinterpret_cast<__nv_bfloat162*>(oh+512)[0]=p;
    p.x=l[2]; p.y=l[3]; reinterpret_cast<__nv_bfloat162*>(oh+512)[1]=p;
}

// ---------------- DPB layer-0 -> bf16 [hi|lo] ----------------
__global__ __launch_bounds__(128) void dpb_in_kernel(const float* __restrict__ Wp,
                                                     const float* __restrict__ bp,
                                                     __nv_bfloat16* __restrict__ out)
{
    int m = blockIdx.x;
    float pp;
    if (m == 0 || m == 4096) pp = 0.f;
    else if (m < 4096)       pp = (float)m;
    else                     pp = (float)(m - 8192);
    float4 w = reinterpret_cast<const float4*>(Wp)[threadIdx.x];
    float4 b = reinterpret_cast<const float4*>(bp)[threadIdx.x];
    float a[4] = { fmaf(pp,w.x,b.x), fmaf(pp,w.y,b.y), fmaf(pp,w.z,b.z), fmaf(pp,w.w,b.w) };
    float s = a[0]*a[0]+a[1]*a[1]+a[2]*a[2]+a[3]*a[3];
    #pragma unroll
    for (int o = 16; o > 0; o >>= 1) s += __shfl_xor_sync(0xffffffffu, s, o);
    __shared__ float ws[4];
    if ((threadIdx.x & 31) == 0) ws[threadIdx.x >> 5] = s;
    __syncthreads();
    float tot = ws[0] + ws[1] + ws[2] + ws[3];
    float scale = 1.0f / (sqrtf(tot) * 0.04419417382415922f + 1e-8f);
    __nv_bfloat16 h[4], l[4];
    #pragma unroll
    for (int i = 0; i < 4; i++) hl_split(fmaxf(a[i]*scale, 0.f), h[i], l[i]);
    __nv_bfloat16* oh = out + (size_t)m * 1024 + threadIdx.x * 4;
    __nv_bfloat162 p;
    p.x=h[0]; p.y=h[1]; reinterpret_cast<__nv_bfloat162*>(oh)[0]=p;
    p.x=h[2]; p.y=h[3]; reinterpret_cast<__nv_bfloat162*>(oh)[1]=p;
    p.x=l[0]; p.y=l[1]; reinterpret_cast<__nv_bfloat162*>(oh+512)[0]=p;
    p.x=l[2]; p.y=l[3]; reinterpret_cast<__nv_bfloat162*>(oh+512)[1]=p;
}

// ---------------- weight split/transpose: W[K,N] fp32 -> [N, 3K] = [Bh|Bh|Bl] ----------------
__global__ void wsplit_kernel(const float* __restrict__ W, __nv_bfloat16* __restrict__ out,
                              int K, int N)
{
    __shared__ float t[32][33];
    int n0 = blockIdx.x * 32, k0 = blockIdx.y * 32;
    int tx = threadIdx.x, ty = threadIdx.y;
    #pragma unroll
    for (int j = 0; j < 32; j += 8)
        t[ty + j][tx] = W[(size_t)(k0 + ty + j) * N + n0 + tx];
    __syncthreads();
    #pragma unroll
    for (int j = 0; j < 32; j += 8) {
        int n = n0 + ty + j, k = k0 + tx;
        __nv_bfloat16 h, l; hl_split(t[tx][ty + j], h, l);
        size_t base = (size_t)n * 3 * K;
        out[base + k] = h; out[base + K + k] = h; out[base + 2*K + k] = l;
    }
}

// ---------------- transposes for the conv path ----------------
// g_v [(b,i),c] -> g_vT [(b,c),i]
__global__ __launch_bounds__(256) void tr_v_kernel()
{
    __shared__ float t[32][33];
    int b = blockIdx.z;
    int c0 = blockIdx.x * 32, r0 = blockIdx.y * 32;
    int tx = threadIdx.x, ty = threadIdx.y;
    #pragma unroll
    for (int j = 0; j < 32; j += 8)
        t[ty + j][tx] = g_v[((size_t)b * N_SEQ + r0 + ty + j) * 512 + c0 + tx];
    __syncthreads();
    #pragma unroll
    for (int j = 0; j < 32; j += 8)
        g_vT[((size_t)b * 512 + c0 + ty + j) * N_SEQ + r0 + tx] = t[tx][ty + j];
}

// g_cT [(b,c),i] -> g_conv2 [(b,i), hi(c) | lo(c)] bf16
__global__ __launch_bounds__(256) void tr_c_kernel()
{
    __shared__ float t[32][33];
    int b = blockIdx.z;
    int c0 = blockIdx.x * 32, r0 = blockIdx.y * 32;
    int tx = threadIdx.x, ty = threadIdx.y;
    #pragma unroll
    for (int j = 0; j < 32; j += 8)
        t[ty + j][tx] = g_cT[((size_t)b * 512 + c0 + ty + j) * N_SEQ + r0 + tx];
    __syncthreads();
    #pragma unroll
    for (int j = 0; j < 32; j += 8) {
        float v = t[tx][ty + j];
        __nv_bfloat16 h, l; hl_split(v, h, l);
        size_t row = (size_t)b * N_SEQ + r0 + ty + j;
        g_conv2[row * 1024 + c0 + tx]       = h;
        g_conv2[row * 1024 + 512 + c0 + tx] = l;
    }
}

// ---------------- mma.sync bf16 GEMM, 128x256 CTA tile, 8 warps @ 64x64 ----------------
// EPI: 0 plain f32 | 1 silu f32 | 2 gate*u -> bf16 hi/lo [M,2N] | 3 +res f32
#define GS   3
#define STB  49152                       // per-stage: 16KB A + 32KB B
#define DSM  (GS * STB + 1024)

template<int EPI>
__global__ __launch_bounds__(256, 1) void mm_kernel(
    const __nv_bfloat16* __restrict__ A2, const __nv_bfloat16* __restrict__ B3,
    const float* __restrict__ bias, const float* __restrict__ gate,
    const float* __restrict__ res, float* __restrict__ Cf,
    __nv_bfloat16* __restrict__ Chl, int M, int N, int K)
{
    extern __shared__ char dsm[];
    int tid = threadIdx.x, lane = tid & 31, wid = tid >> 5;
    int wm = wid & 1, wn = wid >> 1;          // warp tile: rows wm*64, cols wn*64
    uint32_t raw = s2u(dsm);
    uint32_t dbase = (raw + 1023u) & ~1023u;

    int m0 = blockIdx.y * 128, n0 = blockIdx.x * 256;
    int nkk = K >> 6, nk = 3 * nkk;
    size_t rowA = (size_t)K * 4;   // bytes per A2 row (2K bf16)
    size_t rowB = (size_t)K * 6;   // bytes per B3 row (3K bf16)
    const char* Abase = (const char*)A2 + (size_t)m0 * rowA;
    const char* Bbase = (const char*)B3 + (size_t)n0 * rowB;

    // chunk schedule: c in [0,nkk) -> Ah*Bh, [nkk,2nkk) -> Al*Bh, [2nkk,3nkk) -> Ah*Bl
    auto load = [&](int c) {
        int s = c % GS;
        int ac = (c >= 2 * nkk) ? c - 2 * nkk : c;
        uint32_t sA = dbase + s * STB, sB = sA + 16384;
        const char* ga = Abase + (size_t)ac * 128;
        const char* gb = Bbase + (size_t)c * 128;
        #pragma unroll
        for (int i = 0; i < 4; i++) {
            int u = tid + i * 256; int r = u >> 3; int cc = (u & 7) * 16;
            cp16(sA + swz(r * 128 + cc), ga + (size_t)r * rowA + cc);
        }
        #pragma unroll
        for (int i = 0; i < 8; i++) {
            int u = tid + i * 256; int r = u >> 3; int cc = (u & 7) * 16;
            cp16(sB + swz(r * 128 + cc), gb + (size_t)r * rowB + cc);
        }
        asm volatile("cp.async.commit_group;" ::: "memory");
    };

    float acc[4][8][4];
    #pragma unroll
    for (int i = 0; i < 4; i++)
        #pragma unroll
        for (int j = 0; j < 8; j++)
            #pragma unroll
            for (int q = 0; q < 4; q++) acc[i][j][q] = 0.f;

    for (int i = 0; i < GS && i < nk; i++) load(i);

    for (int i = 0; i < nk; i++) {
        int s = i % GS;
        asm volatile("cp.async.wait_group %0;" :: "n"(GS - 1) : "memory");
        __syncthreads();
        uint32_t sA = dbase + s * STB, sB = sA + 16384;
        int t = lane >> 3, l7 = lane & 7;
        #pragma unroll
        for (int kk = 0; kk < 4; kk++) {
            int kb = kk * 16;
            uint32_t af[4][4], bf[4][4];
            #pragma unroll
            for (int im = 0; im < 4; im++) {
                int mrow = wm * 64 + im * 16 + ((t & 1) << 3) + l7;
                int kcol = kb + ((t >> 1) << 3);
                ldm4(af[im], sA + swz((uint32_t)(mrow * 128 + kcol * 2)));
            }
            #pragma unroll
            for (int jn = 0; jn < 4; jn++) {
                int nrow = wn * 64 + jn * 16 + ((t >> 1) << 3) + l7;
                int kcol = kb + ((t & 1) << 3);
                ldm4(bf[jn], sB + swz((uint32_t)(nrow * 128 + kcol * 2)));
            }
            #pragma unroll
            for (int im = 0; im < 4; im++)
                #pragma unroll
                for (int j = 0; j < 8; j++)
                    mmabf(acc[im][j], af[im], bf[j >> 1][(j & 1) * 2], bf[j >> 1][(j & 1) * 2 + 1]);
        }
        __syncthreads();
        if (i + GS < nk) load(i + GS);
    }

    // epilogue: d0,d1 -> row lane/4, cols c,c+1 ; d2,d3 -> row+8
    #pragma unroll
    for (int im = 0; im < 4; im++) {
        #pragma unroll
        for (int j = 0; j < 8; j++) {
            int col = n0 + wn * 64 + j * 8 + (lane & 3) * 2;
            float b0 = bias[col], b1 = bias[col + 1];
            #pragma unroll
            for (int h = 0; h < 2; h++) {
                size_t row = (size_t)m0 + wm * 64 + im * 16 + (lane >> 2) + h * 8;
                size_t idx = row * (size_t)N + col;
                float v0 = acc[im][j][h * 2 + 0] + b0;
                float v1 = acc[im][j][h * 2 + 1] + b1;
                if (EPI == 1) { v0 = v0 / (1.f + __expf(-v0)); v1 = v1 / (1.f + __expf(-v1)); }
                if (EPI == 3) { v0 += res[idx]; v1 += res[idx + 1]; }
                if (EPI == 2) {
                    v0 *= gate[idx]; v1 *= gate[idx + 1];
                    __nv_bfloat16 h0, l0, h1, l1;
                    hl_split(v0, h0, l0); hl_split(v1, h1, l1);
                    __nv_bfloat162 ph; ph.x = h0; ph.y = h1;
                    __nv_bfloat162 pl; pl.x = l0; pl.y = l1;
                    *reinterpret_cast<__nv_bfloat162*>(Chl + row * (size_t)(2 * N) + col)     = ph;
                    *reinterpret_cast<__nv_bfloat162*>(Chl + row * (size_t)(2 * N) + N + col) = pl;
                } else {
                    float2 o; o.x = v0; o.y = v1;
                    *reinterpret_cast<float2*>(Cf + idx) = o;
                }
            }
        }
    }
}

// ---------------- 8192-pt radix-2 FFT (DIF fwd / DIT inv, bitrev spectra) ----------------
// Twiddle hoisting: for len <= 512, j = tid & (len-1) is invariant across a thread's
// 8 butterflies -> one __sincosf per stage instead of 8 (104 -> 34 MUFU pairs).
__device__ __forceinline__ void fft_fwd(float2* z, int tid)
{
    for (int s = 12; s >= 0; --s) {
        int len = 1 << s;
        if (len >= 1024) {
            for (int idx = tid; idx < 4096; idx += 512) {
                int j = idx & (len - 1);
                int i = ((idx >> s) << (s + 1)) + j;
                float2 u = z[i], w = z[i + len];
                z[i] = make_float2(u.x + w.x, u.y + w.y);
                float dx = u.x - w.x, dy = u.y - w.y;
                float sn, cs; __sincosf((-PI_F) * (float)j / (float)len, &sn, &cs);
                z[i + len] = make_float2(dx * cs - dy * sn, dx * sn + dy * cs);
            }
        } else {
            int j = tid & (len - 1);
            float sn, cs; __sincosf((-PI_F) * (float)j / (float)len, &sn, &cs);
            for (int idx = tid; idx < 4096; idx += 512) {
                int i = ((idx >> s) << (s + 1)) + j;
                float2 u = z[i], w = z[i + len];
                z[i] = make_float2(u.x + w.x, u.y + w.y);
                float dx = u.x - w.x, dy = u.y - w.y;
                z[i + len] = make_float2(dx * cs - dy * sn, dx * sn + dy * cs);
            }
        }
        __syncthreads();
    }
}
__device__ __forceinline__ void fft_inv(float2* z, int tid)
{
    for (int s = 0; s <= 12; ++s) {
        int len = 1 << s;
        if (len >= 1024) {
            for (int idx = tid; idx < 4096; idx += 512) {
                int j = idx & (len - 1);
                int i = ((idx >> s) << (s + 1)) + j;
                float sn, cs; __sincosf(PI_F * (float)j / (float)len, &sn, &cs);
                float2 u = z[i], w = z[i + len];
                float tx = w.x * cs - w.y * sn, ty = w.x * sn + w.y * cs;
                z[i]       = make_float2(u.x + tx, u.y + ty);
                z[i + len] = make_float2(u.x - tx, u.y - ty);
            }
        } else {
            int j = tid & (len - 1);
            float sn, cs; __sincosf(PI_F * (float)j / (float)len, &sn, &cs);
            for (int idx = tid; idx < 4096; idx += 512) {
                int i = ((idx >> s) << (s + 1)) + j;
                float2 u = z[i], w = z[i + len];
                float tx = w.x * cs - w.y * sn, ty = w.x * sn + w.y * cs;
                z[i]       = make_float2(u.x + tx, u.y + ty);
                z[i + len] = make_float2(u.x - tx, u.y - ty);
            }
        }
        __syncthreads();
    }
}

__global__ __launch_bounds__(512) void af_kernel()
{
    extern __shared__ float2 z[];
    int c = blockIdx.x, tid = threadIdx.x;
    for (int m = tid; m < N_CIRC; m += 512)
        z[m] = make_float2(g_At[(size_t)m * DMODEL + c], 0.f);
    __syncthreads();
    fft_fwd(z, tid);
    const float inv = 1.0f / 8192.0f;
    for (int k = tid; k < N_CIRC; k += 512) {
        float2 v = z[k];
        g_Af[(size_t)c * N_CIRC + k] = make_float2(v.x * inv, v.y * inv);
    }
}

__global__ __launch_bounds__(512) void conv_kernel()
{
    extern __shared__ float2 z[];
    int bc = blockIdx.x;               // b*512 + c
    int c = bc & 511, tid = threadIdx.x;
    const float* vp = g_vT + (size_t)bc * N_SEQ;
    for (int j = tid; j < N_SEQ; j += 512)
        z[j] = make_float2(vp[j], 0.f);
    for (int j = N_SEQ + tid; j < N_CIRC; j += 512)
        z[j] = make_float2(0.f, 0.f);
    __syncthreads();
    fft_fwd(z, tid);
    const float2* af = g_Af + (size_t)c * N_CIRC;
    for (int k = tid; k < N_CIRC; k += 512) {
        float2 a = af[k], v = z[k];
        z[k] = make_float2(v.x * a.x - v.y * a.y, v.x * a.y + v.y * a.x);
    }
    __syncthreads();
    fft_inv(z, tid);
    float* op = g_cT + (size_t)bc * N_SEQ;
    for (int i = tid; i < N_SEQ; i += 512)
        op[i] = z[i].x;
}

// ---------------- host ----------------
static float* sym_f(const void* s) { void* p = nullptr; cudaGetSymbolAddress(&p, s); return (float*)p; }
static __nv_bfloat16* sym_h(const void* s) { void* p = nullptr; cudaGetSymbolAddress(&p, s); return (__nv_bfloat16*)p; }

extern "C" void kernel_launch(void* const* d_in, const int* in_sizes, int n_in,
                              void* d_out, int out_size)
{
    const float* x   = (const float*)d_in[0];
    const float* Wu  = (const float*)d_in[1];  const float* bu  = (const float*)d_in[2];
    const float* Wv  = (const float*)d_in[3];  const float* bv  = (const float*)d_in[4];
    const float* Wo1 = (const float*)d_in[5];  const float* bo1 = (const float*)d_in[6];
    const float* Wo2 = (const float*)d_in[7];  const float* bo2 = (const float*)d_in[8];
    const float* dWp = (const float*)d_in[9];  const float* dbp = (const float*)d_in[10];
    const float* dW1 = (const float*)d_in[11]; const float* db1 = (const float*)d_in[12];
    const float* dW2 = (const float*)d_in[13]; const float* db2 = (const float*)d_in[14];
    const float* dW3 = (const float*)d_in[15]; const float* db3 = (const float*)d_in[16];
    float* out = (float*)d_out;

    cudaFuncSetAttribute(af_kernel,    cudaFuncAttributeMaxDynamicSharedMemorySize, 65536);
    cudaFuncSetAttribute(conv_kernel,  cudaFuncAttributeMaxDynamicSharedMemorySize, 65536);
    cudaFuncSetAttribute(mm_kernel<0>, cudaFuncAttributeMaxDynamicSharedMemorySize, DSM);
    cudaFuncSetAttribute(mm_kernel<1>, cudaFuncAttributeMaxDynamicSharedMemorySize, DSM);
    cudaFuncSetAttribute(mm_kernel<2>, cudaFuncAttributeMaxDynamicSharedMemorySize, DSM);
    cudaFuncSetAttribute(mm_kernel<3>, cudaFuncAttributeMaxDynamicSharedMemorySize, DSM);

    float* p_u  = sym_f(g_u);   float* p_v  = sym_f(g_v);
    float* p_tb = sym_f(g_tb);  float* p_At = sym_f(g_At);
    __nv_bfloat16* p_xn2  = sym_h(g_xn2);   __nv_bfloat16* p_ta2  = sym_h(g_ta2);
    __nv_bfloat16* p_cv2  = sym_h(g_conv2); __nv_bfloat16* p_gt2  = sym_h(g_gate2);
    __nv_bfloat16* p_Wu3  = sym_h(g_Wu3);   __nv_bfloat16* p_Wv3  = sym_h(g_Wv3);
    __nv_bfloat16* p_Wo13 = sym_h(g_Wo13);  __nv_bfloat16* p_Wo23 = sym_h(g_Wo23);
    __nv_bfloat16* p_dW13 = sym_h(g_dW13);  __nv_bfloat16* p_dW23 = sym_h(g_dW23);
    __nv_bfloat16* p_dW33 = sym_h(g_dW33);

    dim3 wb(32, 8);
    // launch order arranged so ncu (-s 5 -c 1) captures the u-projection GEMM (launch #5)
    wsplit_kernel<<<dim3(1024/32, 512/32),  wb>>>(Wu,  p_Wu3,  512, 1024);   // 0
    wsplit_kernel<<<dim3(512/32,  512/32),  wb>>>(Wv,  p_Wv3,  512, 512);    // 1
    wsplit_kernel<<<dim3(1024/32, 512/32),  wb>>>(Wo1, p_Wo13, 512, 1024);   // 2
    wsplit_kernel<<<dim3(512/32,  1024/32), wb>>>(Wo2, p_Wo23, 1024, 512);   // 3
    srms_hl_kernel<0><<<NROWS, 128>>>(x, p_xn2);                             // 4
    mm_kernel<1><<<dim3(4, 256), 256, DSM>>>(p_xn2, p_Wu3, bu, nullptr, nullptr, p_u, nullptr, NROWS, 1024, 512);  // 5 (profiled)
    mm_kernel<1><<<dim3(2, 256), 256, DSM>>>(p_xn2, p_Wv3, bv, nullptr, nullptr, p_v, nullptr, NROWS, 512, 512);   // 6
    // DPB MLP
    wsplit_kernel<<<dim3(512/32, 512/32), wb>>>(dW1, p_dW13, 512, 512);
    dpb_in_kernel<<<N_CIRC, 128>>>(dWp, dbp, p_ta2);
    mm_kernel<0><<<dim3(2, 64), 256, DSM>>>(p_ta2, p_dW13, db1, nullptr, nullptr, p_tb, nullptr, N_CIRC, 512, 512);
    wsplit_kernel<<<dim3(512/32, 512/32), wb>>>(dW2, p_dW23, 512, 512);
    srms_hl_kernel<1><<<N_CIRC, 128>>>(p_tb, p_ta2);
    mm_kernel<0><<<dim3(2, 64), 256, DSM>>>(p_ta2, p_dW23, db2, nullptr, nullptr, p_tb, nullptr, N_CIRC, 512, 512);
    wsplit_kernel<<<dim3(512/32, 512/32), wb>>>(dW3, p_dW33, 512, 512);
    srms_hl_kernel<1><<<N_CIRC, 128>>>(p_tb, p_ta2);
    mm_kernel<0><<<dim3(2, 64), 256, DSM>>>(p_ta2, p_dW33, db3, nullptr, nullptr, p_At, nullptr, N_CIRC, 512, 512);
    // spectra + convolution (coalesced via transposes)
    af_kernel<<<512, 512, 65536>>>();
    tr_v_kernel<<<dim3(16, 128, 8), dim3(32, 8)>>>();
    conv_kernel<<<NROWS / 8, 512, 65536>>>();
    tr_c_kernel<<<dim3(16, 128, 8), dim3(32, 8)>>>();
    // gated output projections + residual
    mm_kernel<2><<<dim3(4, 256), 256, DSM>>>(p_cv2, p_Wo13, bo1, p_u, nullptr, nullptr, p_gt2, NROWS, 1024, 512);
    mm_kernel<3><<<dim3(2, 256), 256, DSM>>>(p_gt2, p_Wo23, bo2, nullptr, x, out, nullptr, NROWS, 512, 1024);
}